// round 10
// baseline (speedup 1.0000x reference)
#include <cuda_runtime.h>
#include <cuda_bf16.h>
#include <cstdint>

#define NUM_CLASSES 100000
#define EMBED 512
#define BATCH_N 4096
#define LAMBDA_C 0.01f
#define ALPHA_C 0.1f

#define NCS ((size_t)NUM_CLASSES * EMBED)   // 51,200,000 floats
#define NCHUNK (NCS / 4)                     // 12,800,000 float4 chunks

// Per-class chains. Zero-initialized at module load; fused kernel restores
// zeros after use, so the all-zero invariant holds every call (no memset).
// Encoding: g_head[c] == 0 -> untouched; == i+1 -> sample i is chain head.
__device__ int g_head[NUM_CLASSES];
__device__ int g_next[BATCH_N];

// 1) build chains + zero loss slot
__global__ __launch_bounds__(256)
void build_kernel(const int* __restrict__ y, float* __restrict__ loss) {
    int i = blockIdx.x * blockDim.x + threadIdx.x;
    if (i == 0) *loss = 0.0f;
    if (i < BATCH_N) {
        int c = y[i];
        int old = atomicExch(&g_head[c], i + 1);
        g_next[i] = old;
    }
}

// 2) fused streaming pass, one block (128 thr) per class row.
//    Copy path uses ALIGNED STG.128 on the shifted grid: thread t stores dst
//    elements [r*512+3+4t .. +6+4t] (16B-aligned since dst = out+1).
//    Touched rows (g_head>0) skip the copy store and are written entirely by
//    the rare path (sole writer per address -> no syncs, no races).
__global__ __launch_bounds__(128)
void fused_copy_apply_kernel(const float* __restrict__ src,
                             const float4* __restrict__ src4,
                             const float4* __restrict__ batch4,
                             float* __restrict__ dst,
                             float* __restrict__ loss) {
    const int r = blockIdx.x;
    const int t = threadIdx.x;                 // 0..127
    const size_t cbase = (size_t)r * 128;      // first float4 chunk of row r

    const int h = g_head[r];                   // block-uniform broadcast load

    // main aligned load: chunk cbase+1+t (elements r*512+4+4t .. +7+4t)
    size_t cidx = cbase + 1 + t;
    if (cidx >= NCHUNK) cidx = NCHUNK - 1;     // clamp (only very last thread)
    float4 A = __ldcs(src4 + cidx);
    // straddler scalar: element r*512+3+4t (same lines as neighbors' A loads)
    float s = __ldcs(src + (size_t)r * EMBED + 3 + 4 * t);

    const size_t e = (size_t)r * EMBED + 3 + 4 * t;   // first dst element

    if (t < 127) {
        if (h == 0) {
            float4 v = make_float4(s, A.x, A.y, A.z);
            __stcs(reinterpret_cast<float4*>(dst + e), v);
        }
    } else {
        // thread 127: float4 spans row r elem 511 + row r+1 elems 0..2
        if (r == NUM_CLASSES - 1) {
            if (h == 0) dst[e] = s;            // last element only
        } else {
            const int h2 = g_head[r + 1];
            if (h == 0 && h2 == 0) {
                float4 v = make_float4(s, A.x, A.y, A.z);
                __stcs(reinterpret_cast<float4*>(dst + e), v);
            } else if (h == 0) {               // row r+1 touched
                dst[e] = s;                    // elem 511 of row r only
            } else if (h2 == 0) {              // row r touched
                dst[e + 1] = A.x;              // elems 0..2 of row r+1
                dst[e + 2] = A.y;
                dst[e + 3] = A.z;
            } // both touched: rare paths cover everything
        }
    }

    // head of the whole tensor: elements 0..2 of row 0
    if (r == 0 && t == 0 && h == 0) {
        dst[0] = src[0];
        dst[1] = src[1];
        dst[2] = src[2];
    }

    // rare path: row touched -> sole writer of the full row
    if (h > 0) {
        float4 c4 = src4[cbase + t];           // row-aligned center values
        float ax = 0.f, ay = 0.f, az = 0.f, aw = 0.f, ls = 0.f;
        int sc = h;
        while (sc > 0) {
            float4 b4 = batch4[(size_t)(sc - 1) * (EMBED / 4) + t];
            float dx = b4.x - c4.x;
            float dy = b4.y - c4.y;
            float dz = b4.z - c4.z;
            float dw = b4.w - c4.w;
            ax += dx; ay += dy; az += dz; aw += dw;
            ls += dx * dx + dy * dy + dz * dz + dw * dw;
            sc = g_next[sc - 1];
        }
        float* d = dst + (size_t)r * EMBED + 4 * t;   // misaligned: scalars
        d[0] = c4.x + ALPHA_C * ax;
        d[1] = c4.y + ALPHA_C * ay;
        d[2] = c4.z + ALPHA_C * az;
        d[3] = c4.w + ALPHA_C * aw;

        // loss reduce (block-uniform branch -> warp-uniform)
        #pragma unroll
        for (int off = 16; off > 0; off >>= 1)
            ls += __shfl_xor_sync(0xFFFFFFFFu, ls, off);
        if ((t & 31) == 0)
            atomicAdd(loss, ls * (LAMBDA_C / (float)BATCH_N));

        if (t == 0) g_head[r] = 0;             // restore zero-invariant
    }
}

extern "C" void kernel_launch(void* const* d_in, const int* in_sizes, int n_in,
                              void* d_out, int out_size) {
    const int*   y       = (const int*)d_in[0];
    const float* batch   = (const float*)d_in[1];
    const float* centers = (const float*)d_in[2];

    float* out = (float*)d_out;

    float* loss_ptr;
    float* new_centers;
    if (out_size == (int)(NCS + 1)) {
        loss_ptr = out;
        new_centers = out + 1;
    } else {
        new_centers = out;
        loss_ptr = out + NCS;
    }

    // 1) chains + loss zero (g_head all-zero by maintained invariant)
    build_kernel<<<(BATCH_N + 255) / 256, 256>>>(y, loss_ptr);

    // 2) fused streaming copy (aligned STG.128) + sparse overwrite
    fused_copy_apply_kernel<<<NUM_CLASSES, 128>>>(
        centers,
        reinterpret_cast<const float4*>(centers),
        reinterpret_cast<const float4*>(batch),
        new_centers, loss_ptr);
}